// round 12
// baseline (speedup 1.0000x reference)
#include <cuda_runtime.h>
#include <cuda_bf16.h>

#define BB 4
#define TT 1024
#define CC 768
#define NH 12
#define HD 64
#define BT (BB*TT)
#define N_QKV (3*CC)

// Scratch: tf32 bit patterns (q pre-scaled by log2e/8). g_v is D-MAJOR [B,NH,HD,TT].
__device__ __align__(256) float g_q[BB*NH*TT*HD];
__device__ __align__(256) float g_k[BB*NH*TT*HD];
__device__ __align__(256) float g_v[BB*NH*HD*TT];
__device__ __align__(256) float g_y[BT*CC];
__device__ __align__(256) float g_xa[BT*CC];
__device__ __align__(256) float g_wqt[N_QKV*CC];   // Wqkv transposed [N][K]
__device__ __align__(256) float g_wpt[CC*CC];      // Wproj transposed [N][K]

__device__ __forceinline__ unsigned f2tf32(float f) {
    unsigned r; asm("cvt.rna.tf32.f32 %0, %1;" : "=r"(r) : "f"(f)); return r;
}
__device__ __forceinline__ float ex2(float x) {
    float r; asm("ex2.approx.ftz.f32 %0, %1;" : "=f"(r) : "f"(x)); return r;
}
__device__ __forceinline__ void mma8(float* c, const unsigned* a, const unsigned* b) {
    asm volatile(
        "mma.sync.aligned.m16n8k8.row.col.f32.tf32.tf32.f32 "
        "{%0,%1,%2,%3}, {%4,%5,%6,%7}, {%8,%9}, {%0,%1,%2,%3};"
        : "+f"(c[0]), "+f"(c[1]), "+f"(c[2]), "+f"(c[3])
        : "r"(a[0]), "r"(a[1]), "r"(a[2]), "r"(a[3]), "r"(b[0]), "r"(b[1]));
}
__device__ __forceinline__ unsigned smem_u32(const void* p) {
    return (unsigned)__cvta_generic_to_shared(p);
}
#define CPA(dst, src) asm volatile("cp.async.cg.shared.global [%0], [%1], 16;" :: "r"(dst), "l"(src))
#define CPC()  asm volatile("cp.async.commit_group;")
#define CPW0() asm volatile("cp.async.wait_group 0;")
#define CPW1() asm volatile("cp.async.wait_group 1;")
#define LDSM4(d0,d1,d2,d3,a) \
    asm volatile("ldmatrix.sync.aligned.m8n8.x4.shared.b16 {%0,%1,%2,%3}, [%4];" \
                 : "=r"(d0),"=r"(d1),"=r"(d2),"=r"(d3) : "r"(a))

// ---------------------------------------------------------------------------
__global__ void cvt_kernel(const float* __restrict__ s, float* __restrict__ d, int n4)
{
    int i = blockIdx.x * blockDim.x + threadIdx.x;
    if (i < n4) {
        float4 v = ((const float4*)s)[i];
        ((uint4*)d)[i] = make_uint4(f2tf32(v.x), f2tf32(v.y), f2tf32(v.z), f2tf32(v.w));
    }
}

// Transpose + tf32 cvt: W [K][N] fp32 -> Wt [N][K=CC] tf32 bits
__global__ void tcvt_kernel(const float* __restrict__ W, float* __restrict__ Wt, int N)
{
    __shared__ float t[32][33];
    int n0 = blockIdx.x * 32, k0 = blockIdx.y * 32;
    int tx = threadIdx.x, ty = threadIdx.y;  // 32 x 8
    #pragma unroll
    for (int i = 0; i < 4; i++)
        t[ty + i*8][tx] = W[(size_t)(k0 + ty + i*8) * N + n0 + tx];
    __syncthreads();
    #pragma unroll
    for (int i = 0; i < 4; i++)
        Wt[(size_t)(n0 + ty + i*8) * CC + k0 + tx] =
            __uint_as_float(f2tf32(t[tx][ty + i*8]));
}

// ---------------------------------------------------------------------------
// GEMM mainloop: CTA tile 128(m) x 64(n), warp tile 32x32, k-chunk 32,
// 2-stage cp.async, ldmatrix fragments. 3 CTAs/SM (24 warps).
// ---------------------------------------------------------------------------
#define GLD 36
#define A_TSZ (128*GLD)
#define B_TSZ (64*GLD)
#define GEMM_SMEM (2*(A_TSZ+B_TSZ)*4)

extern __shared__ unsigned dynsm[];

__device__ __forceinline__ void gemm_mainloop(
    const float* __restrict__ A, const float* __restrict__ Bm,
    int m0, int n0, float acc[2][4][4])
{
    const int tid  = threadIdx.x;
    const int warp = tid >> 5;
    const int lane = tid & 31;
    const int wm = warp >> 1, wn = warp & 1;

    const unsigned aBase = smem_u32(dynsm);
    const unsigned bBase = aBase + 2*A_TSZ*4;

    // loader maps (element offsets fit 32-bit)
    unsigned aoff[4], asrc[4], boff[2], bsrc[2];
    #pragma unroll
    for (int s = 0; s < 4; s++) {
        int idx = tid + s * 256;
        int row = idx >> 3, k4 = (idx & 7) * 4;
        aoff[s] = row * GLD + k4;
        asrc[s] = (unsigned)(m0 + row) * CC + k4;
    }
    #pragma unroll
    for (int s = 0; s < 2; s++) {
        int idx = tid + s * 256;
        int row = idx >> 3, k4 = (idx & 7) * 4;
        boff[s] = row * GLD + k4;
        bsrc[s] = (unsigned)(n0 + row) * CC + k4;
    }

    // ldmatrix per-lane addresses
    const int a_r = lane & 15, a_c = (lane >> 4) * 4;
    const int b_r = (lane & 7) + ((lane & 16) >> 1);
    const int b_c = (lane & 8) ? 4 : 0;
    unsigned aAd[2], bAd[2];
    #pragma unroll
    for (int mt = 0; mt < 2; mt++)
        aAd[mt] = aBase + ((wm*32 + mt*16 + a_r) * GLD + a_c) * 4;
    #pragma unroll
    for (int np = 0; np < 2; np++)
        bAd[np] = bBase + ((wn*32 + np*16 + b_r) * GLD + b_c) * 4;

#define GEMM_ISSUE(k0, buf) do {                                             \
        _Pragma("unroll")                                                    \
        for (int s = 0; s < 4; s++)                                          \
            CPA(aBase + ((buf)*A_TSZ + aoff[s])*4u, A + asrc[s] + (k0));     \
        _Pragma("unroll")                                                    \
        for (int s = 0; s < 2; s++)                                          \
            CPA(bBase + ((buf)*B_TSZ + boff[s])*4u, Bm + bsrc[s] + (k0));    \
    } while (0)

    GEMM_ISSUE(0, 0);
    CPC();

    const int NIT = CC / 32;
    int buf = 0;
    for (int it = 0; it < NIT; it++) {
        CPW0();
        __syncthreads();
        if (it + 1 < NIT) { GEMM_ISSUE((it + 1) * 32, buf ^ 1); CPC(); }

        const unsigned ao = (unsigned)(buf * A_TSZ * 4);
        const unsigned bo = (unsigned)(buf * B_TSZ * 4);
        #pragma unroll
        for (int ks = 0; ks < 4; ks++) {
            const unsigned kb = ks * 32;
            unsigned af[2][4], bf[4][2];
            LDSM4(af[0][0], af[0][1], af[0][2], af[0][3], aAd[0] + ao + kb);
            LDSM4(af[1][0], af[1][1], af[1][2], af[1][3], aAd[1] + ao + kb);
            LDSM4(bf[0][0], bf[0][1], bf[1][0], bf[1][1], bAd[0] + bo + kb);
            LDSM4(bf[2][0], bf[2][1], bf[3][0], bf[3][1], bAd[1] + bo + kb);
            #pragma unroll
            for (int mt = 0; mt < 2; mt++)
                #pragma unroll
                for (int nt = 0; nt < 4; nt++)
                    mma8(acc[mt][nt], af[mt], bf[nt]);
        }
        buf ^= 1;
    }
#undef GEMM_ISSUE
}

// ---------------------------------------------------------------------------
// Kernel 1: qkv -> q/k token-major (q pre-scaled log2e/8), v D-MAJOR
// ---------------------------------------------------------------------------
__global__ __launch_bounds__(256, 3) void qkv_gemm_kernel(const float* __restrict__ bias)
{
    const int tid = threadIdx.x, warp = tid >> 5, lane = tid & 31;
    const int g = lane >> 2, t = lane & 3;
    const int wm = warp >> 1, wn = warp & 1;
    const int m0 = blockIdx.y * 128, n0 = blockIdx.x * 64;

    float acc[2][4][4];
    #pragma unroll
    for (int i = 0; i < 2; i++)
        #pragma unroll
        for (int j = 0; j < 4; j++)
            #pragma unroll
            for (int e = 0; e < 4; e++) acc[i][j][e] = 0.f;

    gemm_mainloop(g_xa, g_wqt, m0, n0, acc);

    const int which = n0 / CC;
    const float sc = (which == 0) ? (0.125f * 1.4426950408889634f) : 1.0f;

    #pragma unroll
    for (int mt = 0; mt < 2; mt++) {
        int r0 = m0 + wm * 32 + mt * 16 + g;
        #pragma unroll
        for (int nt = 0; nt < 4; nt++) {
            int cg = n0 + wn * 32 + nt * 8 + t * 2;
            int c0 = cg - which * CC;
            int h = c0 >> 6, d = c0 & 63;
            float b0v = bias[cg], b1v = bias[cg + 1];
            int ba = r0 >> 10, ta = r0 & 1023;
            int bb_ = (r0 + 8) >> 10, tb = (r0 + 8) & 1023;
            if (which == 2) {   // v: d-major [B,NH,HD,TT]
                float* vb_ = g_v + (size_t)((ba * NH + h) * HD) * TT;
                float* vb2 = g_v + (size_t)((bb_ * NH + h) * HD) * TT;
                vb_[(size_t)d * TT + ta]       = __uint_as_float(f2tf32(acc[mt][nt][0] + b0v));
                vb_[(size_t)(d+1) * TT + ta]   = __uint_as_float(f2tf32(acc[mt][nt][1] + b1v));
                vb2[(size_t)d * TT + tb]       = __uint_as_float(f2tf32(acc[mt][nt][2] + b0v));
                vb2[(size_t)(d+1) * TT + tb]   = __uint_as_float(f2tf32(acc[mt][nt][3] + b1v));
            } else {
                float* dst = (which == 0) ? g_q : g_k;
                *(uint2*)&dst[(size_t)(((ba * NH + h) * TT) + ta) * HD + d] =
                    make_uint2(f2tf32((acc[mt][nt][0] + b0v) * sc),
                               f2tf32((acc[mt][nt][1] + b1v) * sc));
                *(uint2*)&dst[(size_t)(((bb_ * NH + h) * TT) + tb) * HD + d] =
                    make_uint2(f2tf32((acc[mt][nt][2] + b0v) * sc),
                               f2tf32((acc[mt][nt][3] + b1v) * sc));
            }
        }
    }
}

// ---------------------------------------------------------------------------
// Kernel 3: out = y @ Wproj + bproj (fp32 out)
// ---------------------------------------------------------------------------
__global__ __launch_bounds__(256, 3) void proj_gemm_kernel(const float* __restrict__ bias,
                                                           float* __restrict__ out)
{
    const int tid = threadIdx.x, warp = tid >> 5, lane = tid & 31;
    const int g = lane >> 2, t = lane & 3;
    const int wm = warp >> 1, wn = warp & 1;
    const int m0 = blockIdx.y * 128, n0 = blockIdx.x * 64;

    float acc[2][4][4];
    #pragma unroll
    for (int i = 0; i < 2; i++)
        #pragma unroll
        for (int j = 0; j < 4; j++)
            #pragma unroll
            for (int e = 0; e < 4; e++) acc[i][j][e] = 0.f;

    gemm_mainloop(g_y, g_wpt, m0, n0, acc);

    #pragma unroll
    for (int mt = 0; mt < 2; mt++) {
        int r0 = m0 + wm * 32 + mt * 16 + g;
        #pragma unroll
        for (int nt = 0; nt < 4; nt++) {
            int cg = n0 + wn * 32 + nt * 8 + t * 2;
            float b0v = bias[cg], b1v = bias[cg + 1];
            *(float2*)&out[(size_t)r0 * CC + cg] =
                make_float2(acc[mt][nt][0] + b0v, acc[mt][nt][1] + b1v);
            *(float2*)&out[(size_t)(r0 + 8) * CC + cg] =
                make_float2(acc[mt][nt][2] + b0v, acc[mt][nt][3] + b1v);
        }
    }
}

// ---------------------------------------------------------------------------
// Kernel 2: causal flash attention (unchanged from R11).
// CTA = 128 q rows x (head, batch). 8 warps x (16 rows x 64 cols).
// ---------------------------------------------------------------------------
#define QS_LD 68
#define KS_LD 68
#define VS_LD 68
#define OFF_K (128*QS_LD)
#define OFF_V (OFF_K + 2*64*KS_LD)
#define ATTN_SMEM ((OFF_V + 2*64*VS_LD) * 4)

__global__ __launch_bounds__(256, 2) void attn_kernel()
{
    unsigned* Qs = dynsm;
    const int tid  = threadIdx.x;
    const int warp = tid >> 5;
    const int lane = tid & 31;
    const int g = lane >> 2, t = lane & 3;
    const int rm = warp * 16;
    const int r0 = rm + g, r1 = rm + g + 8;

    const int qt = gridDim.x - 1 - blockIdx.x;
    const int h  = blockIdx.y;
    const int b  = blockIdx.z;

    const float* qb = g_q + (size_t)((b * NH + h) * TT) * HD;
    const float* kb = g_k + (size_t)((b * NH + h) * TT) * HD;
    const float* vb = g_v + (size_t)((b * NH + h) * HD) * TT;   // d-major

    const unsigned qB = smem_u32(Qs);
    const unsigned kB = qB + OFF_K * 4;
    const unsigned vB = qB + OFF_V * 4;

    const int a_r = lane & 15, a_c = (lane >> 4) * 4;
    const int b_r = (lane & 7) + ((lane & 16) >> 1);
    const int b_c = (lane & 8) ? 4 : 0;
    const unsigned qAd = qB + ((rm + a_r) * QS_LD + a_c) * 4;
    unsigned kAd[4], vAd[4];
    #pragma unroll
    for (int j = 0; j < 4; j++) {
        kAd[j] = kB + ((j*16 + b_r) * KS_LD + b_c) * 4;
        vAd[j] = vB + ((j*16 + b_r) * VS_LD + b_c) * 4;
    }

    int krw[4], kcc[4];
    #pragma unroll
    for (int s = 0; s < 4; s++) {
        int idx = tid + s * 256;
        krw[s] = idx >> 4;
        kcc[s] = (idx & 15) * 4;
    }

#define KV_ISSUE(j, bufo) do {                                                       \
        _Pragma("unroll")                                                            \
        for (int s = 0; s < 4; s++) {                                                \
            CPA(kB + ((bufo)*64*KS_LD + krw[s]*KS_LD + kcc[s])*4u,                   \
                kb + (size_t)((j) * 64 + krw[s]) * HD + kcc[s]);                     \
            CPA(vB + ((bufo)*64*VS_LD + krw[s]*VS_LD + kcc[s])*4u,                   \
                vb + (size_t)krw[s] * TT + (j) * 64 + kcc[s]);                       \
        }                                                                            \
    } while (0)

    #pragma unroll
    for (int s = 0; s < 8; s++) {
        int idx = tid + s * 256;
        int row = idx >> 4, c4 = (idx & 15) * 4;
        CPA(qB + (row * QS_LD + c4) * 4u, qb + (size_t)(qt * 128 + row) * HD + c4);
    }
    KV_ISSUE(0, 0);
    CPC();

    float mo0 = -1e30f, mo1 = -1e30f, lo0 = 0.f, lo1 = 0.f;
    float o[8][4];
    #pragma unroll
    for (int i = 0; i < 8; i++)
        #pragma unroll
        for (int e = 0; e < 4; e++) o[i][e] = 0.f;

    const int R0g = qt * 128 + r0;
    const int R1g = qt * 128 + r1;
    const unsigned srcA = (lane & 28) | ((lane & 3) >> 1);
    const unsigned srcB = srcA + 2;
    const bool selHi = (t & 1);

    const int NT = 2 * qt + 2;
    for (int j0 = 0; j0 < NT; j0++) {
        const int cur = j0 & 1;
        CPW0();
        __syncthreads();
        if (j0 + 1 < NT) { KV_ISSUE(j0 + 1, cur ^ 1); CPC(); }

        const unsigned kbo = (unsigned)(cur * 64 * KS_LD * 4);
        const unsigned vbo = (unsigned)(cur * 64 * VS_LD * 4);

        float sacc[8][4];
        #pragma unroll
        for (int nt = 0; nt < 8; nt++)
            #pragma unroll
            for (int e = 0; e < 4; e++) sacc[nt][e] = 0.f;

        #pragma unroll
        for (int ks = 0; ks < 8; ks++) {
            const unsigned kk4 = ks * 32;
            unsigned af[4], bf[8][2];
            LDSM4(af[0], af[1], af[2], af[3], qAd + kk4);
            #pragma unroll
            for (int j = 0; j < 4; j++)
                LDSM4(bf[2*j][0], bf[2*j][1], bf[2*j+1][0], bf[2*j+1][1],
                      kAd[j] + kbo + kk4);
            #pragma unroll
            for (int nt = 0; nt < 8; nt++)
                mma8(sacc[nt], af, bf[nt]);
        }

        if (j0 >= 2 * qt) {
            #pragma unroll
            for (int nt = 0; nt < 8; nt++) {
                int col = j0 * 64 + nt * 8 + t * 2;
                if (col     > R0g) sacc[nt][0] = -1e30f;
                if (col + 1 > R0g) sacc[nt][1] = -1e30f;
                if (col     > R1g) sacc[nt][2] = -1e30f;
                if (col + 1 > R1g) sacc[nt][3] = -1e30f;
            }
        }

        float tm0 = sacc[0][0], tm1 = sacc[0][2];
        #pragma unroll
        for (int nt = 0; nt < 8; nt++) {
            tm0 = fmaxf(tm0, fmaxf(sacc[nt][0], sacc[nt][1]));
            tm1 = fmaxf(tm1, fmaxf(sacc[nt][2], sacc[nt][3]));
        }
        tm0 = fmaxf(tm0, __shfl_xor_sync(0xffffffffu, tm0, 1));
        tm0 = fmaxf(tm0, __shfl_xor_sync(0xffffffffu, tm0, 2));
        tm1 = fmaxf(tm1, __shfl_xor_sync(0xffffffffu, tm1, 1));
        tm1 = fmaxf(tm1, __shfl_xor_sync(0xffffffffu, tm1, 2));

        const float mn0 = fmaxf(mo0, tm0);
        const float mn1 = fmaxf(mo1, tm1);
        const float al0 = ex2(mo0 - mn0);
        const float al1 = ex2(mo1 - mn1);

        float s0 = 0.f, s1 = 0.f;
        #pragma unroll
        for (int nt = 0; nt < 8; nt++) {
            float p00 = ex2(sacc[nt][0] - mn0);
            float p01 = ex2(sacc[nt][1] - mn0);
            float p10 = ex2(sacc[nt][2] - mn1);
            float p11 = ex2(sacc[nt][3] - mn1);
            s0 += p00 + p01; s1 += p10 + p11;
            sacc[nt][0] = __uint_as_float(f2tf32(p00));
            sacc[nt][1] = __uint_as_float(f2tf32(p01));
            sacc[nt][2] = __uint_as_float(f2tf32(p10));
            sacc[nt][3] = __uint_as_float(f2tf32(p11));
        }
        s0 += __shfl_xor_sync(0xffffffffu, s0, 1);
        s0 += __shfl_xor_sync(0xffffffffu, s0, 2);
        s1 += __shfl_xor_sync(0xffffffffu, s1, 1);
        s1 += __shfl_xor_sync(0xffffffffu, s1, 2);
        lo0 = lo0 * al0 + s0;  mo0 = mn0;
        lo1 = lo1 * al1 + s1;  mo1 = mn1;

        #pragma unroll
        for (int dt = 0; dt < 8; dt++) {
            o[dt][0] *= al0; o[dt][1] *= al0;
            o[dt][2] *= al1; o[dt][3] *= al1;
        }

        #pragma unroll
        for (int kc = 0; kc < 8; kc++) {
            unsigned af[4], bf[8][2];
            unsigned v0, v1;
            v0 = __shfl_sync(0xffffffffu, __float_as_uint(sacc[kc][0]), srcA);
            v1 = __shfl_sync(0xffffffffu, __float_as_uint(sacc[kc][1]), srcA);
            af[0] = selHi ? v1 : v0;
            v0 = __shfl_sync(0xffffffffu, __float_as_uint(sacc[kc][2]), srcA);
            v1 = __shfl_sync(0xffffffffu, __float_as_uint(sacc[kc][3]), srcA);
            af[1] = selHi ? v1 : v0;
            v0 = __shfl_sync(0xffffffffu, __float_as_uint(sacc[kc][0]), srcB);
            v1 = __shfl_sync(0xffffffffu, __float_as_uint(sacc[kc][1]), srcB);
            af[2] = selHi ? v1 : v0;
            v0 = __shfl_sync(0xffffffffu, __float_as_uint(sacc[kc][2]), srcB);
            v1 = __shfl_sync(0xffffffffu, __float_as_uint(sacc[kc][3]), srcB);
            af[3] = selHi ? v1 : v0;
            #pragma unroll
            for (int j = 0; j < 4; j++)
                LDSM4(bf[2*j][0], bf[2*j][1], bf[2*j+1][0], bf[2*j+1][1],
                      vAd[j] + vbo + kc * 32);
            #pragma unroll
            for (int dt = 0; dt < 8; dt++)
                mma8(o[dt], af, bf[dt]);
        }
    }

    const float inv0 = 1.f / lo0;
    const float inv1 = 1.f / lo1;
    #pragma unroll
    for (int dt = 0; dt < 8; dt++) {
        int col = h * HD + dt * 8 + t * 2;
        *(uint2*)&g_y[(size_t)(b * TT + R0g) * CC + col] =
            make_uint2(f2tf32(o[dt][0] * inv0), f2tf32(o[dt][1] * inv0));
        *(uint2*)&g_y[(size_t)(b * TT + R1g) * CC + col] =
            make_uint2(f2tf32(o[dt][2] * inv1), f2tf32(o[dt][3] * inv1));
    }
#undef KV_ISSUE
}

// ---------------------------------------------------------------------------
extern "C" void kernel_launch(void* const* d_in, const int* in_sizes, int n_in,
                              void* d_out, int out_size)
{
    const float* x     = (const float*)d_in[0];
    const float* Wqkv  = (const float*)d_in[1];
    const float* bqkv  = (const float*)d_in[2];
    const float* Wproj = (const float*)d_in[3];
    const float* bproj = (const float*)d_in[4];
    float* out = (float*)d_out;

    cudaFuncSetAttribute(attn_kernel, cudaFuncAttributeMaxDynamicSharedMemorySize, ATTN_SMEM);
    cudaFuncSetAttribute(qkv_gemm_kernel, cudaFuncAttributeMaxDynamicSharedMemorySize, GEMM_SMEM);
    cudaFuncSetAttribute(proj_gemm_kernel, cudaFuncAttributeMaxDynamicSharedMemorySize, GEMM_SMEM);

    float* xa; cudaGetSymbolAddress((void**)&xa, g_xa);
    float* wq; cudaGetSymbolAddress((void**)&wq, g_wqt);
    float* wp; cudaGetSymbolAddress((void**)&wp, g_wpt);

    cvt_kernel<<<(BT*CC/4 + 255)/256, 256>>>(x, xa, BT*CC/4);
    tcvt_kernel<<<dim3(N_QKV/32, CC/32), dim3(32, 8)>>>(Wqkv, wq, N_QKV);
    tcvt_kernel<<<dim3(CC/32, CC/32), dim3(32, 8)>>>(Wproj, wp, CC);

    qkv_gemm_kernel<<<dim3(N_QKV/64, BT/128), 256, GEMM_SMEM>>>(bqkv);
    attn_kernel<<<dim3(TT/128, NH, BB), 256, ATTN_SMEM>>>();
    proj_gemm_kernel<<<dim3(CC/64, BT/128), 256, GEMM_SMEM>>>(bproj, out);
}

// round 14
// speedup vs baseline: 1.0441x; 1.0441x over previous
#include <cuda_runtime.h>
#include <cuda_bf16.h>

#define BB 4
#define TT 1024
#define CC 768
#define NH 12
#define HD 64
#define BT (BB*TT)
#define N_QKV (3*CC)

// Scratch: tf32 bit patterns (q pre-scaled by log2e/8). g_v is D-MAJOR [B,NH,HD,TT].
__device__ __align__(256) float g_q[BB*NH*TT*HD];
__device__ __align__(256) float g_k[BB*NH*TT*HD];
__device__ __align__(256) float g_v[BB*NH*HD*TT];
__device__ __align__(256) float g_y[BT*CC];
__device__ __align__(256) float g_xa[BT*CC];
__device__ __align__(256) float g_wqt[N_QKV*CC];   // Wqkv transposed [N][K]
__device__ __align__(256) float g_wpt[CC*CC];      // Wproj transposed [N][K]

__device__ __forceinline__ unsigned f2tf32(float f) {
    unsigned r; asm("cvt.rna.tf32.f32 %0, %1;" : "=r"(r) : "f"(f)); return r;
}
__device__ __forceinline__ float ex2(float x) {
    float r; asm("ex2.approx.ftz.f32 %0, %1;" : "=f"(r) : "f"(x)); return r;
}
__device__ __forceinline__ void mma8(float* c, const unsigned* a, const unsigned* b) {
    asm volatile(
        "mma.sync.aligned.m16n8k8.row.col.f32.tf32.tf32.f32 "
        "{%0,%1,%2,%3}, {%4,%5,%6,%7}, {%8,%9}, {%0,%1,%2,%3};"
        : "+f"(c[0]), "+f"(c[1]), "+f"(c[2]), "+f"(c[3])
        : "r"(a[0]), "r"(a[1]), "r"(a[2]), "r"(a[3]), "r"(b[0]), "r"(b[1]));
}
__device__ __forceinline__ unsigned smem_u32(const void* p) {
    return (unsigned)__cvta_generic_to_shared(p);
}
#define CPA(dst, src) asm volatile("cp.async.cg.shared.global [%0], [%1], 16;" :: "r"(dst), "l"(src))
#define CPC()  asm volatile("cp.async.commit_group;")
#define CPW0() asm volatile("cp.async.wait_group 0;")
#define CPW1() asm volatile("cp.async.wait_group 1;")
#define LDSM4(d0,d1,d2,d3,a) \
    asm volatile("ldmatrix.sync.aligned.m8n8.x4.shared.b16 {%0,%1,%2,%3}, [%4];" \
                 : "=r"(d0),"=r"(d1),"=r"(d2),"=r"(d3) : "r"(a))

// ---------------------------------------------------------------------------
__global__ void cvt_kernel(const float* __restrict__ s, float* __restrict__ d, int n4)
{
    int i = blockIdx.x * blockDim.x + threadIdx.x;
    if (i < n4) {
        float4 v = ((const float4*)s)[i];
        ((uint4*)d)[i] = make_uint4(f2tf32(v.x), f2tf32(v.y), f2tf32(v.z), f2tf32(v.w));
    }
}

// Transpose + tf32 cvt: W [K][N] fp32 -> Wt [N][K=CC] tf32 bits
__global__ void tcvt_kernel(const float* __restrict__ W, float* __restrict__ Wt, int N)
{
    __shared__ float t[32][33];
    int n0 = blockIdx.x * 32, k0 = blockIdx.y * 32;
    int tx = threadIdx.x, ty = threadIdx.y;  // 32 x 8
    #pragma unroll
    for (int i = 0; i < 4; i++)
        t[ty + i*8][tx] = W[(size_t)(k0 + ty + i*8) * N + n0 + tx];
    __syncthreads();
    #pragma unroll
    for (int i = 0; i < 4; i++)
        Wt[(size_t)(n0 + ty + i*8) * CC + k0 + tx] =
            __uint_as_float(f2tf32(t[tx][ty + i*8]));
}

#define GLD 36
extern __shared__ unsigned dynsm[];

// ---------------------------------------------------------------------------
// Kernel 1: qkv GEMM, CTA tile 128(m) x 256(n), 512 threads / 16 warps
// (2m x 8n, warp tile 64x32), k-chunk 32, 2-stage cp.async, ldmatrix.
// ---------------------------------------------------------------------------
#define QA_TSZ (128*GLD)
#define QB_TSZ (256*GLD)
#define QKV_SMEM (2*(QA_TSZ+QB_TSZ)*4)

__global__ __launch_bounds__(512, 1) void qkv_gemm_kernel(const float* __restrict__ bias)
{
    const int tid = threadIdx.x, warp = tid >> 5, lane = tid & 31;
    const int g = lane >> 2, t = lane & 3;
    const int wm = warp >> 3, wn = warp & 7;
    const int m0 = blockIdx.y * 128, n0 = blockIdx.x * 256;

    const unsigned aBase = smem_u32(dynsm);
    const unsigned bBase = aBase + 2*QA_TSZ*4;

    // loader maps
    unsigned aoff[2], asrc[2], boff[4], bsrc[4];
    #pragma unroll
    for (int s = 0; s < 2; s++) {
        int idx = tid + s * 512;
        int row = idx >> 3, k4 = (idx & 7) * 4;
        aoff[s] = row * GLD + k4;
        asrc[s] = (unsigned)(m0 + row) * CC + k4;
    }
    #pragma unroll
    for (int s = 0; s < 4; s++) {
        int idx = tid + s * 512;
        int row = idx >> 3, k4 = (idx & 7) * 4;
        boff[s] = row * GLD + k4;
        bsrc[s] = (unsigned)(n0 + row) * CC + k4;
    }

    // ldmatrix per-lane addresses
    const int a_r = lane & 15, a_c = (lane >> 4) * 4;
    const int b_r = (lane & 7) + ((lane & 16) >> 1);
    const int b_c = (lane & 8) ? 4 : 0;
    unsigned aAd[4], bAd[2];
    #pragma unroll
    for (int mt = 0; mt < 4; mt++)
        aAd[mt] = aBase + ((wm*64 + mt*16 + a_r) * GLD + a_c) * 4;
    #pragma unroll
    for (int np = 0; np < 2; np++)
        bAd[np] = bBase + ((wn*32 + np*16 + b_r) * GLD + b_c) * 4;

    float acc[4][4][4];
    #pragma unroll
    for (int i = 0; i < 4; i++)
        #pragma unroll
        for (int j = 0; j < 4; j++)
            #pragma unroll
            for (int e = 0; e < 4; e++) acc[i][j][e] = 0.f;

#define QISSUE(k0, buf) do {                                                   \
        _Pragma("unroll")                                                      \
        for (int s = 0; s < 2; s++)                                            \
            CPA(aBase + ((buf)*QA_TSZ + aoff[s])*4u, g_xa + asrc[s] + (k0));   \
        _Pragma("unroll")                                                      \
        for (int s = 0; s < 4; s++)                                            \
            CPA(bBase + ((buf)*QB_TSZ + boff[s])*4u, g_wqt + bsrc[s] + (k0));  \
    } while (0)

    QISSUE(0, 0);
    CPC();

    const int NIT = CC / 32;
    int buf = 0;
    for (int it = 0; it < NIT; it++) {
        CPW0();
        __syncthreads();
        if (it + 1 < NIT) { QISSUE((it + 1) * 32, buf ^ 1); CPC(); }

        const unsigned ao = (unsigned)(buf * QA_TSZ * 4);
        const unsigned bo = (unsigned)(buf * QB_TSZ * 4);
        #pragma unroll
        for (int ks = 0; ks < 4; ks++) {
            const unsigned kb = ks * 32;
            unsigned af[4][4], bf[4][2];
            #pragma unroll
            for (int mt = 0; mt < 4; mt++)
                LDSM4(af[mt][0], af[mt][1], af[mt][2], af[mt][3], aAd[mt] + ao + kb);
            LDSM4(bf[0][0], bf[0][1], bf[1][0], bf[1][1], bAd[0] + bo + kb);
            LDSM4(bf[2][0], bf[2][1], bf[3][0], bf[3][1], bAd[1] + bo + kb);
            #pragma unroll
            for (int mt = 0; mt < 4; mt++)
                #pragma unroll
                for (int nt = 0; nt < 4; nt++)
                    mma8(acc[mt][nt], af[mt], bf[nt]);
        }
        buf ^= 1;
    }
#undef QISSUE

    const int which = n0 / CC;
    const float sc = (which == 0) ? (0.125f * 1.4426950408889634f) : 1.0f;

    #pragma unroll
    for (int mt = 0; mt < 4; mt++) {
        int r0 = m0 + wm * 64 + mt * 16 + g;
        #pragma unroll
        for (int nt = 0; nt < 4; nt++) {
            int cg = n0 + wn * 32 + nt * 8 + t * 2;
            int c0 = cg - which * CC;
            int h = c0 >> 6, d = c0 & 63;
            float b0v = bias[cg], b1v = bias[cg + 1];
            int ba = r0 >> 10, ta = r0 & 1023;
            int bb_ = (r0 + 8) >> 10, tb = (r0 + 8) & 1023;
            if (which == 2) {   // v: d-major [B,NH,HD,TT]
                float* vb_ = g_v + (size_t)((ba * NH + h) * HD) * TT;
                float* vb2 = g_v + (size_t)((bb_ * NH + h) * HD) * TT;
                vb_[(size_t)d * TT + ta]       = __uint_as_float(f2tf32(acc[mt][nt][0] + b0v));
                vb_[(size_t)(d+1) * TT + ta]   = __uint_as_float(f2tf32(acc[mt][nt][1] + b1v));
                vb2[(size_t)d * TT + tb]       = __uint_as_float(f2tf32(acc[mt][nt][2] + b0v));
                vb2[(size_t)(d+1) * TT + tb]   = __uint_as_float(f2tf32(acc[mt][nt][3] + b1v));
            } else {
                float* dst = (which == 0) ? g_q : g_k;
                *(uint2*)&dst[(size_t)(((ba * NH + h) * TT) + ta) * HD + d] =
                    make_uint2(f2tf32((acc[mt][nt][0] + b0v) * sc),
                               f2tf32((acc[mt][nt][1] + b1v) * sc));
                *(uint2*)&dst[(size_t)(((bb_ * NH + h) * TT) + tb) * HD + d] =
                    make_uint2(f2tf32((acc[mt][nt][2] + b0v) * sc),
                               f2tf32((acc[mt][nt][3] + b1v) * sc));
            }
        }
    }
}

// ---------------------------------------------------------------------------
// Kernel 3: proj GEMM, R11 config: CTA 128x128, 256 thr / 8 warps (2m x 4n),
// 3-stage cp.async, ldmatrix. 2 CTAs/SM.
// ---------------------------------------------------------------------------
#define P_TSZ (128*GLD)
#define PROJ_SMEM (3*2*P_TSZ*4)

__global__ __launch_bounds__(256, 2) void proj_gemm_kernel(const float* __restrict__ bias,
                                                           float* __restrict__ out)
{
    const int tid = threadIdx.x, warp = tid >> 5, lane = tid & 31;
    const int g = lane >> 2, t = lane & 3;
    const int wm = warp >> 2, wn = warp & 3;
    const int m0 = blockIdx.y * 128, n0 = blockIdx.x * 128;

    const unsigned aBase = smem_u32(dynsm);
    const unsigned bBase = aBase + 3*P_TSZ*4;

    unsigned off[4], asrc[4], bsrc[4];
    #pragma unroll
    for (int s = 0; s < 4; s++) {
        int idx = tid + s * 256;
        int row = idx >> 3, k4 = (idx & 7) * 4;
        off[s] = row * GLD + k4;
        asrc[s] = (unsigned)(m0 + row) * CC + k4;
        bsrc[s] = (unsigned)(n0 + row) * CC + k4;
    }

    const int a_r = lane & 15, a_c = (lane >> 4) * 4;
    const int b_r = (lane & 7) + ((lane & 16) >> 1);
    const int b_c = (lane & 8) ? 4 : 0;
    unsigned aAd[4], bAd[2];
    #pragma unroll
    for (int mt = 0; mt < 4; mt++)
        aAd[mt] = aBase + ((wm*64 + mt*16 + a_r) * GLD + a_c) * 4;
    #pragma unroll
    for (int np = 0; np < 2; np++)
        bAd[np] = bBase + ((wn*32 + np*16 + b_r) * GLD + b_c) * 4;

    float acc[4][4][4];
    #pragma unroll
    for (int i = 0; i < 4; i++)
        #pragma unroll
        for (int j = 0; j < 4; j++)
            #pragma unroll
            for (int e = 0; e < 4; e++) acc[i][j][e] = 0.f;

#define PISSUE(k0, buf) do {                                                 \
        _Pragma("unroll")                                                    \
        for (int s = 0; s < 4; s++) {                                        \
            CPA(aBase + ((buf)*P_TSZ + off[s])*4u, g_y + asrc[s] + (k0));    \
            CPA(bBase + ((buf)*P_TSZ + off[s])*4u, g_wpt + bsrc[s] + (k0));  \
        }                                                                    \
    } while (0)

    PISSUE(0, 0);  CPC();
    PISSUE(32, 1); CPC();

    const int NIT = CC / 32;
    int buf = 0;
    for (int it = 0; it < NIT; it++) {
        if (it < NIT - 1) CPW1(); else CPW0();
        __syncthreads();
        if (it + 2 < NIT) {
            int nb = buf + 2; if (nb >= 3) nb -= 3;
            PISSUE((it + 2) * 32, nb);
            CPC();
        }
        const unsigned ao = (unsigned)(buf * P_TSZ * 4);
        #pragma unroll
        for (int ks = 0; ks < 4; ks++) {
            const unsigned kb = ao + ks * 32;
            unsigned af[4][4], bf[4][2];
            #pragma unroll
            for (int mt = 0; mt < 4; mt++)
                LDSM4(af[mt][0], af[mt][1], af[mt][2], af[mt][3], aAd[mt] + kb);
            LDSM4(bf[0][0], bf[0][1], bf[1][0], bf[1][1], bAd[0] + kb);
            LDSM4(bf[2][0], bf[2][1], bf[3][0], bf[3][1], bAd[1] + kb);
            #pragma unroll
            for (int mt = 0; mt < 4; mt++)
                #pragma unroll
                for (int nt = 0; nt < 4; nt++)
                    mma8(acc[mt][nt], af[mt], bf[nt]);
        }
        if (++buf == 3) buf = 0;
    }
#undef PISSUE

    #pragma unroll
    for (int mt = 0; mt < 4; mt++) {
        int r0 = m0 + wm * 64 + mt * 16 + g;
        #pragma unroll
        for (int nt = 0; nt < 4; nt++) {
            int cg = n0 + wn * 32 + nt * 8 + t * 2;
            float b0v = bias[cg], b1v = bias[cg + 1];
            *(float2*)&out[(size_t)r0 * CC + cg] =
                make_float2(acc[mt][nt][0] + b0v, acc[mt][nt][1] + b1v);
            *(float2*)&out[(size_t)(r0 + 8) * CC + cg] =
                make_float2(acc[mt][nt][2] + b0v, acc[mt][nt][3] + b1v);
        }
    }
}

// ---------------------------------------------------------------------------
// Kernel 2: causal flash attention (unchanged from R11).
// ---------------------------------------------------------------------------
#define QS_LD 68
#define KS_LD 68
#define VS_LD 68
#define OFF_K (128*QS_LD)
#define OFF_V (OFF_K + 2*64*KS_LD)
#define ATTN_SMEM ((OFF_V + 2*64*VS_LD) * 4)

__global__ __launch_bounds__(256, 2) void attn_kernel()
{
    unsigned* Qs = dynsm;
    const int tid  = threadIdx.x;
    const int warp = tid >> 5;
    const int lane = tid & 31;
    const int g = lane >> 2, t = lane & 3;
    const int rm = warp * 16;
    const int r0 = rm + g, r1 = rm + g + 8;

    const int qt = gridDim.x - 1 - blockIdx.x;
    const int h  = blockIdx.y;
    const int b  = blockIdx.z;

    const float* qb = g_q + (size_t)((b * NH + h) * TT) * HD;
    const float* kb = g_k + (size_t)((b * NH + h) * TT) * HD;
    const float* vb = g_v + (size_t)((b * NH + h) * HD) * TT;   // d-major

    const unsigned qB = smem_u32(Qs);
    const unsigned kB = qB + OFF_K * 4;
    const unsigned vB = qB + OFF_V * 4;

    const int a_r = lane & 15, a_c = (lane >> 4) * 4;
    const int b_r = (lane & 7) + ((lane & 16) >> 1);
    const int b_c = (lane & 8) ? 4 : 0;
    const unsigned qAd = qB + ((rm + a_r) * QS_LD + a_c) * 4;
    unsigned kAd[4], vAd[4];
    #pragma unroll
    for (int j = 0; j < 4; j++) {
        kAd[j] = kB + ((j*16 + b_r) * KS_LD + b_c) * 4;
        vAd[j] = vB + ((j*16 + b_r) * VS_LD + b_c) * 4;
    }

    int krw[4], kcc[4];
    #pragma unroll
    for (int s = 0; s < 4; s++) {
        int idx = tid + s * 256;
        krw[s] = idx >> 4;
        kcc[s] = (idx & 15) * 4;
    }

#define KV_ISSUE(j, bufo) do {                                                       \
        _Pragma("unroll")                                                            \
        for (int s = 0; s < 4; s++) {                                                \
            CPA(kB + ((bufo)*64*KS_LD + krw[s]*KS_LD + kcc[s])*4u,                   \
                kb + (size_t)((j) * 64 + krw[s]) * HD + kcc[s]);                     \
            CPA(vB + ((bufo)*64*VS_LD + krw[s]*VS_LD + kcc[s])*4u,                   \
                vb + (size_t)krw[s] * TT + (j) * 64 + kcc[s]);                       \
        }                                                                            \
    } while (0)

    #pragma unroll
    for (int s = 0; s < 8; s++) {
        int idx = tid + s * 256;
        int row = idx >> 4, c4 = (idx & 15) * 4;
        CPA(qB + (row * QS_LD + c4) * 4u, qb + (size_t)(qt * 128 + row) * HD + c4);
    }
    KV_ISSUE(0, 0);
    CPC();

    float mo0 = -1e30f, mo1 = -1e30f, lo0 = 0.f, lo1 = 0.f;
    float o[8][4];
    #pragma unroll
    for (int i = 0; i < 8; i++)
        #pragma unroll
        for (int e = 0; e < 4; e++) o[i][e] = 0.f;

    const int R0g = qt * 128 + r0;
    const int R1g = qt * 128 + r1;
    const unsigned srcA = (lane & 28) | ((lane & 3) >> 1);
    const unsigned srcB = srcA + 2;
    const bool selHi = (t & 1);

    const int NT = 2 * qt + 2;
    for (int j0 = 0; j0 < NT; j0++) {
        const int cur = j0 & 1;
        CPW0();
        __syncthreads();
        if (j0 + 1 < NT) { KV_ISSUE(j0 + 1, cur ^ 1); CPC(); }

        const unsigned kbo = (unsigned)(cur * 64 * KS_LD * 4);
        const unsigned vbo = (unsigned)(cur * 64 * VS_LD * 4);

        float sacc[8][4];
        #pragma unroll
        for (int nt = 0; nt < 8; nt++)
            #pragma unroll
            for (int e = 0; e < 4; e++) sacc[nt][e] = 0.f;

        #pragma unroll
        for (int ks = 0; ks < 8; ks++) {
            const unsigned kk4 = ks * 32;
            unsigned af[4], bf[8][2];
            LDSM4(af[0], af[1], af[2], af[3], qAd + kk4);
            #pragma unroll
            for (int j = 0; j < 4; j++)
                LDSM4(bf[2*j][0], bf[2*j][1], bf[2*j+1][0], bf[2*j+1][1],
                      kAd[j] + kbo + kk4);
            #pragma unroll
            for (int nt = 0; nt < 8; nt++)
                mma8(sacc[nt], af, bf[nt]);
        }

        if (j0 >= 2 * qt) {
            #pragma unroll
            for (int nt = 0; nt < 8; nt++) {
                int col = j0 * 64 + nt * 8 + t * 2;
                if (col     > R0g) sacc[nt][0] = -1e30f;
                if (col + 1 > R0g) sacc[nt][1] = -1e30f;
                if (col     > R1g) sacc[nt][2] = -1e30f;
                if (col + 1 > R1g) sacc[nt][3] = -1e30f;
            }
        }

        float tm0 = sacc[0][0], tm1 = sacc[0][2];
        #pragma unroll
        for (int nt = 0; nt < 8; nt++) {
            tm0 = fmaxf(tm0, fmaxf(sacc[nt][0], sacc[nt][1]));
            tm1 = fmaxf(tm1, fmaxf(sacc[nt][2], sacc[nt][3]));
        }
        tm0 = fmaxf(tm0, __shfl_xor_sync(0xffffffffu, tm0, 1));
        tm0 = fmaxf(tm0, __shfl_xor_sync(0xffffffffu, tm0, 2));
        tm1 = fmaxf(tm1, __shfl_xor_sync(0xffffffffu, tm1, 1));
        tm1 = fmaxf(tm1, __shfl_xor_sync(0xffffffffu, tm1, 2));

        const float mn0 = fmaxf(mo0, tm0);
        const float mn1 = fmaxf(mo1, tm1);
        const float al0 = ex2(mo0 - mn0);
        const float al1 = ex2(mo1 - mn1);

        float s0 = 0.f, s1 = 0.f;
        #pragma unroll
        for (int nt = 0; nt < 8; nt++) {
            float p00 = ex2(sacc[nt][0] - mn0);
            float p01 = ex2(sacc[nt][1] - mn0);
            float p10 = ex2(sacc[nt][2] - mn1);
            float p11 = ex2(sacc[nt][3] - mn1);
            s0 += p00 + p01; s1 += p10 + p11;
            sacc[nt][0] = __uint_as_float(f2tf32(p00));
            sacc[nt][1] = __uint_as_float(f2tf32(p01));
            sacc[nt][2] = __uint_as_float(f2tf32(p10));
            sacc[nt][3] = __uint_as_float(f2tf32(p11));
        }
        s0 += __shfl_xor_sync(0xffffffffu, s0, 1);
        s0 += __shfl_xor_sync(0xffffffffu, s0, 2);
        s1 += __shfl_xor_sync(0xffffffffu, s1, 1);
        s1 += __shfl_xor_sync(0xffffffffu, s1, 2);
        lo0 = lo0 * al0 + s0;  mo0 = mn0;
        lo1 = lo1 * al1 + s1;  mo1 = mn1;

        #pragma unroll
        for (int dt = 0; dt < 8; dt++) {
            o[dt][0] *= al0; o[dt][1] *= al0;
            o[dt][2] *= al1; o[dt][3] *= al1;
        }

        #pragma unroll
        for (int kc = 0; kc < 8; kc++) {
            unsigned af[4], bf[8][2];
            unsigned v0, v1;
            v0 = __shfl_sync(0xffffffffu, __float_as_uint(sacc[kc][0]), srcA);
            v1 = __shfl_sync(0xffffffffu, __float_as_uint(sacc[kc][1]), srcA);
            af[0] = selHi ? v1 : v0;
            v0 = __shfl_sync(0xffffffffu, __float_as_uint(sacc[kc][2]), srcA);
            v1 = __shfl_sync(0xffffffffu, __float_as_uint(sacc[kc][3]), srcA);
            af[1] = selHi ? v1 : v0;
            v0 = __shfl_sync(0xffffffffu, __float_as_uint(sacc[kc][0]), srcB);
            v1 = __shfl_sync(0xffffffffu, __float_as_uint(sacc[kc][1]), srcB);
            af[2] = selHi ? v1 : v0;
            v0 = __shfl_sync(0xffffffffu, __float_as_uint(sacc[kc][2]), srcB);
            v1 = __shfl_sync(0xffffffffu, __float_as_uint(sacc[kc][3]), srcB);
            af[3] = selHi ? v1 : v0;
            #pragma unroll
            for (int j = 0; j < 4; j++)
                LDSM4(bf[2*j][0], bf[2*j][1], bf[2*j+1][0], bf[2*j+1][1],
                      vAd[j] + vbo + kc * 32);
            #pragma unroll
            for (int dt = 0; dt < 8; dt++)
                mma8(o[dt], af, bf[dt]);
        }
    }

    const float inv0 = 1.f / lo0;
    const float inv1 = 1.f / lo1;
    #pragma unroll
    for (int dt = 0; dt < 8; dt++) {
        int col = h * HD + dt * 8 + t * 2;
        *(uint2*)&g_y[(size_t)(b * TT + R0g) * CC + col] =
            make_uint2(f2tf32(o[dt][0] * inv0), f2tf32(o[dt][1] * inv0));
        *(uint2*)&g_y[(size_t)(b * TT + R1g) * CC + col] =
            make_uint2(f2tf32(o[dt][2] * inv1), f2tf32(o[dt][3] * inv1));
    }
#undef KV_ISSUE
}

// ---------------------------------------------------------------------------
extern "C" void kernel_launch(void* const* d_in, const int* in_sizes, int n_in,
                              void* d_out, int out_size)
{
    const float* x     = (const float*)d_in[0];
    const float* Wqkv  = (const float*)d_in[1];
    const float* bqkv  = (const float*)d_in[2];
    const float* Wproj = (const float*)d_in[3];
    const float* bproj = (const float*)d_in[4];
    float* out = (float*)d_out;

    cudaFuncSetAttribute(attn_kernel, cudaFuncAttributeMaxDynamicSharedMemorySize, ATTN_SMEM);
    cudaFuncSetAttribute(qkv_gemm_kernel, cudaFuncAttributeMaxDynamicSharedMemorySize, QKV_SMEM);
    cudaFuncSetAttribute(proj_gemm_kernel, cudaFuncAttributeMaxDynamicSharedMemorySize, PROJ_SMEM);

    float* xa; cudaGetSymbolAddress((void**)&xa, g_xa);
    float* wq; cudaGetSymbolAddress((void**)&wq, g_wqt);
    float* wp; cudaGetSymbolAddress((void**)&wp, g_wpt);

    cvt_kernel<<<(BT*CC/4 + 255)/256, 256>>>(x, xa, BT*CC/4);
    tcvt_kernel<<<dim3(N_QKV/32, CC/32), dim3(32, 8)>>>(Wqkv, wq, N_QKV);
    tcvt_kernel<<<dim3(CC/32, CC/32), dim3(32, 8)>>>(Wproj, wp, CC);

    qkv_gemm_kernel<<<dim3(N_QKV/256, BT/128), 512, QKV_SMEM>>>(bqkv);
    attn_kernel<<<dim3(TT/128, NH, BB), 256, ATTN_SMEM>>>();
    proj_gemm_kernel<<<dim3(CC/128, BT/128), 256, PROJ_SMEM>>>(bproj, out);
}